// round 15
// baseline (speedup 1.0000x reference)
#include <cuda_runtime.h>
#include <cuda_bf16.h>
#include <math_constants.h>
#include <cstdint>

#define NN 100000
#define NPAD 100096          // 782 * 128
#define DD 128
#define EE 1600000
#define NEG_SLOPE 0.2f
#define NB ((NN + 255) / 256)

// ---------------- scratch (device globals; no runtime allocation) ----------
__device__ float g_xl[NPAD * DD];
__device__ float g_xr[NPAD * DD];
__device__ __nv_bfloat16 g_Ah[NPAD * DD];
__device__ __nv_bfloat16 g_Al[NPAD * DD];
__device__ __nv_bfloat16 g_Bh[6][DD * DD];  // W^T [n][k] row-major, hi
__device__ __nv_bfloat16 g_Bl[6][DD * DD];  // ... lo
__device__ int   g_src[EE];
__device__ int   g_dst[EE];
__device__ int   g_deg[NN];
__device__ int   g_off[NN];
__device__ int   g_cur[NN];
__device__ int   g_psrc[EE];
__device__ int   g_bsum[NB];
__device__ int   g_bbase[512];
__device__ int   g_is64;

// ---------------- helpers ----------------------------------------------------
__device__ __forceinline__ uint32_t smem_u32(const void* p) {
    uint32_t a;
    asm("{ .reg .u64 t; cvta.to.shared.u64 t, %1; cvt.u32.u64 %0, t; }" : "=r"(a) : "l"(p));
    return a;
}
__device__ __forceinline__ void ldmatrix_x4(uint32_t& r0, uint32_t& r1,
                                            uint32_t& r2, uint32_t& r3, uint32_t addr) {
    asm volatile("ldmatrix.sync.aligned.m8n8.x4.shared.b16 {%0,%1,%2,%3}, [%4];"
        : "=r"(r0), "=r"(r1), "=r"(r2), "=r"(r3) : "r"(addr));
}
__device__ __forceinline__ void mma_bf16(float* c, const uint32_t* a, const uint32_t* b) {
    asm volatile("mma.sync.aligned.m16n8k16.row.col.f32.bf16.bf16.f32 "
        "{%0,%1,%2,%3}, {%4,%5,%6,%7}, {%8,%9}, {%0,%1,%2,%3};"
        : "+f"(c[0]), "+f"(c[1]), "+f"(c[2]), "+f"(c[3])
        : "r"(a[0]), "r"(a[1]), "r"(a[2]), "r"(a[3]), "r"(b[0]), "r"(b[1]));
}
__device__ __forceinline__ void cp_async16(uint32_t saddr, const void* gptr) {
    asm volatile("cp.async.cg.shared.global [%0], [%1], 16;" :: "r"(saddr), "l"(gptr));
}
__device__ __forceinline__ void cp_commit() {
    asm volatile("cp.async.commit_group;");
}
template <int N>
__device__ __forceinline__ void cp_wait() {
    asm volatile("cp.async.wait_group %0;" :: "n"(N));
}
__device__ __forceinline__ void split1(float v, __nv_bfloat16& hi, __nv_bfloat16& lo) {
    hi = __float2bfloat16(v);
    lo = __float2bfloat16(v - __bfloat162float(hi));
}

// ---------------- dtype detection + fused convert/hist ---------------------
__global__ void detect_kernel(const int* __restrict__ ei32) {
    int t = threadIdx.x;
    int v = ei32[2 * t + 1];
    unsigned ok = __ballot_sync(0xffffffffu, v == 0);
    __shared__ int nz;
    if (t == 0) nz = 0;
    __syncthreads();
    if ((t & 31) == 0 && ok != 0xffffffffu) atomicAdd(&nz, 1);
    __syncthreads();
    if (t == 0) g_is64 = (nz == 0) ? 1 : 0;
}

// g_deg must be zeroed (memsetAsync) before this runs
__global__ void convert_hist(const void* __restrict__ ei) {
    int i = blockIdx.x * blockDim.x + threadIdx.x;
    if (i >= 2 * EE) return;
    int v;
    if (g_is64) v = (int)((const long long*)ei)[i];
    else        v = ((const int*)ei)[i];
    if (i < EE) g_src[i] = v;
    else { g_dst[i - EE] = v; atomicAdd(&g_deg[v], 1); }
}

__global__ void blocksum_kernel() {
    int b = blockIdx.x * 256 + threadIdx.x;
    int d = (b < NN) ? g_deg[b] : 0;
#pragma unroll
    for (int o = 16; o > 0; o >>= 1) d += __shfl_xor_sync(0xffffffffu, d, o);
    __shared__ int ws[8];
    if ((threadIdx.x & 31) == 0) ws[threadIdx.x >> 5] = d;
    __syncthreads();
    if (threadIdx.x == 0) {
        int t = 0;
#pragma unroll
        for (int i = 0; i < 8; i++) t += ws[i];
        g_bsum[blockIdx.x] = t;
    }
}

__global__ void scanbsum_kernel() {
    __shared__ int s[512];
    int t = threadIdx.x;
    int v = (t < NB) ? g_bsum[t] : 0;
    s[t] = v;
    __syncthreads();
    for (int o = 1; o < 512; o <<= 1) {
        int a = (t >= o) ? s[t - o] : 0;
        __syncthreads();
        s[t] += a;
        __syncthreads();
    }
    g_bbase[t] = s[t] - v;
}

__global__ void binscan_kernel() {
    __shared__ int s[256];
    int t = threadIdx.x;
    int b = blockIdx.x * 256 + t;
    int d = (b < NN) ? g_deg[b] : 0;
    s[t] = d;
    __syncthreads();
    for (int o = 1; o < 256; o <<= 1) {
        int a = (t >= o) ? s[t - o] : 0;
        __syncthreads();
        s[t] += a;
        __syncthreads();
    }
    if (b < NN) {
        int off = g_bbase[blockIdx.x] + s[t] - d;
        g_off[b] = off;
        g_cur[b] = off;
    }
}

__global__ void scatter_kernel() {
    int e = blockIdx.x * blockDim.x + threadIdx.x;
    if (e >= EE) return;
    int d = g_dst[e];
    int pos = atomicAdd(&g_cur[d], 1);
    g_psrc[pos] = g_src[e];
}

// ---------------- W conversion: transpose + split ---------------------------
__global__ void conv_W(const float* __restrict__ Wl, const float* __restrict__ Wr) {
    int idx = blockIdx.x * 256 + threadIdx.x;   // 0..98303
    int m = idx >> 14;
    int r = idx & 16383;
    int k = r >> 7;
    int n = r & 127;
    int layer = m >> 1;
    const float* src = (m & 1) ? Wr : Wl;
    float v = src[layer * 16384 + k * 128 + n];
    __nv_bfloat16 hi, lo;
    split1(v, hi, lo);
    g_Bh[m][n * 128 + k] = hi;
    g_Bl[m][n * 128 + k] = lo;
}

// ---------------- x conversion (layer 0 A input) ---------------------------
__global__ void conv_x(const float* __restrict__ x) {
    int idx = blockIdx.x * blockDim.x + threadIdx.x;
    if (idx >= NN * 32) return;
    float4 v = ((const float4*)x)[idx];
    __nv_bfloat16 hx, hy, hz, hw, lx, ly, lz, lw;
    split1(v.x, hx, lx); split1(v.y, hy, ly);
    split1(v.z, hz, lz); split1(v.w, hw, lw);
    __nv_bfloat162* ph = (__nv_bfloat162*)g_Ah + idx * 2;
    __nv_bfloat162* pl = (__nv_bfloat162*)g_Al + idx * 2;
    ph[0] = __nv_bfloat162(hx, hy); ph[1] = __nv_bfloat162(hz, hw);
    pl[0] = __nv_bfloat162(lx, ly); pl[1] = __nv_bfloat162(lz, lw);
}

// ---------------- persistent tensor-core GEMM ------------------------------
// Grid (148, 2), 2 CTA/SM, one wave. B (hi+lo) loaded ONCE per CTA into a
// persistent smem region (272B row stride, conflict-free); A double-buffered
// via cp.async over 4 K-chunks per row-block; each CTA loops 5-6 row-blocks.
#define CROW 80
#define A_SEG 10240
#define A_BUF 20480
#define B_OFF 40960
#define B_TYPE 34816
#define GEMM_SMEM 110592

__global__ void __launch_bounds__(256, 2) gemm_pers(int layer) {
    extern __shared__ char smem[];
    const int tid = threadIdx.x;
    const int wid = tid >> 5;
    const int lane = tid & 31;
    const int mat = layer * 2 + blockIdx.y;

    const int m0 = (wid >> 2) * 64;
    const int n0 = (wid & 3) * 32;

    const uint32_t sbase = smem_u32(smem);
    const uint32_t a_row = m0 + (lane & 15);
    const uint32_t a_coff = ((lane >> 4) << 4);
    const int quad = lane >> 3;
    const uint32_t b_row = n0 + ((quad >> 1) << 3) + (lane & 7);
    const uint32_t b_coff = ((quad & 1) << 4);

    const char* aHg = (const char*)g_Ah;
    const char* aLg = (const char*)g_Al;
    const char* bHg = (const char*)g_Bh[mat];
    const char* bLg = (const char*)g_Bl[mat];

    // one-time persistent B load: 2 types x 128 rows x 16 chunks of 16B
#pragma unroll
    for (int p = 0; p < 16; p++) {
        int o = tid + p * 256;          // 0..4095
        int type = o >> 11;
        int r = (o >> 4) & 127;
        int cg = o & 15;
        const char* g = (type ? bLg : bHg) + r * 256 + cg * 16;
        cp_async16(sbase + B_OFF + type * B_TYPE + r * 272 + cg * 16, g);
    }
    cp_commit();

    float* __restrict__ C = (blockIdx.y == 0) ? g_xl : g_xr;

    for (int rb = blockIdx.x; rb < NPAD / 128; rb += 148) {
        const int rowBase = rb * 128;

        float acc[4][4][4];
#pragma unroll
        for (int i = 0; i < 4; i++)
#pragma unroll
            for (int j = 0; j < 4; j++)
#pragma unroll
                for (int q = 0; q < 4; q++) acc[i][j][q] = 0.0f;

        auto load_chunk = [&](int kc, int buf) {
#pragma unroll
            for (int p = 0; p < 4; p++) {
                int o = tid + p * 256;      // 0..1023
                int seg = o >> 9;           // 0 = AH, 1 = AL
                int r = (o >> 2) & 127;
                int j = o & 3;
                const char* g = (seg ? aLg : aHg)
                    + ((long long)(rowBase + r) * 256 + kc * 64 + j * 16);
                cp_async16(sbase + buf * A_BUF + seg * A_SEG + r * CROW + j * 16, g);
            }
            cp_commit();
        };

        load_chunk(0, 0);

#pragma unroll
        for (int kc = 0; kc < 4; kc++) {
            if (kc < 3) load_chunk(kc + 1, (kc + 1) & 1);
            if (kc < 3) cp_wait<1>(); else cp_wait<0>();
            __syncthreads();

            const uint32_t ab = sbase + (kc & 1) * A_BUF;
#pragma unroll
            for (int ks = 0; ks < 2; ks++) {
                const uint32_t k0b = ks * 32;
                uint32_t bHf[4][2], bLf[4][2];
#pragma unroll
                for (int p = 0; p < 2; p++) {
                    uint32_t bd = sbase + B_OFF + (b_row + p * 16) * 272
                                + kc * 64 + k0b + b_coff;
                    uint32_t r0, r1, r2, r3;
                    ldmatrix_x4(r0, r1, r2, r3, bd);
                    bHf[p * 2][0] = r0; bHf[p * 2][1] = r1;
                    bHf[p * 2 + 1][0] = r2; bHf[p * 2 + 1][1] = r3;
                    ldmatrix_x4(r0, r1, r2, r3, bd + B_TYPE);
                    bLf[p * 2][0] = r0; bLf[p * 2][1] = r1;
                    bLf[p * 2 + 1][0] = r2; bLf[p * 2 + 1][1] = r3;
                }
#pragma unroll
                for (int mi = 0; mi < 4; mi++) {
                    uint32_t aHf[4], aLf[4];
                    uint32_t ad = ab + (a_row + mi * 16) * CROW + k0b + a_coff;
                    ldmatrix_x4(aHf[0], aHf[1], aHf[2], aHf[3], ad);
                    ldmatrix_x4(aLf[0], aLf[1], aLf[2], aLf[3], ad + A_SEG);
#pragma unroll
                    for (int ni = 0; ni < 4; ni++) {
                        mma_bf16(acc[mi][ni], aHf, bHf[ni]);
                        mma_bf16(acc[mi][ni], aLf, bHf[ni]);
                        mma_bf16(acc[mi][ni], aHf, bLf[ni]);
                    }
                }
            }
            if (kc < 3) __syncthreads();   // last chunk: epilogue touches no smem
        }

#pragma unroll
        for (int mi = 0; mi < 4; mi++) {
#pragma unroll
            for (int ni = 0; ni < 4; ni++) {
                int row0 = rowBase + m0 + mi * 16 + (lane >> 2);
                int col = n0 + ni * 8 + (lane & 3) * 2;
                if (row0 < NN)
                    *(float2*)&C[row0 * 128 + col] = make_float2(acc[mi][ni][0], acc[mi][ni][1]);
                int row1 = row0 + 8;
                if (row1 < NN)
                    *(float2*)&C[row1 * 128 + col] = make_float2(acc[mi][ni][2], acc[mi][ni][3]);
            }
        }
        __syncthreads();   // all warps done with buf reads before next rb reload
    }
}

// ---------------- fused node kernel: zero-reference softmax, unroll-4 ------
__device__ __forceinline__ float edge_dot(float4 v, float4 xr4, float4 w4) {
    float z, p;
    z = v.x + xr4.x; z = (z > 0.f) ? z : NEG_SLOPE * z; p = z * w4.x;
    z = v.y + xr4.y; z = (z > 0.f) ? z : NEG_SLOPE * z; p = fmaf(z, w4.y, p);
    z = v.z + xr4.z; z = (z > 0.f) ? z : NEG_SLOPE * z; p = fmaf(z, w4.z, p);
    z = v.w + xr4.w; z = (z > 0.f) ? z : NEG_SLOPE * z; p = fmaf(z, w4.w, p);
    return p;
}

__global__ void __launch_bounds__(64) node_fused(
    const float* __restrict__ att,
    const float* __restrict__ bias,
    float* __restrict__ outp, int sel)
{
    int warp = (blockIdx.x * blockDim.x + threadIdx.x) >> 5;
    int lane = threadIdx.x & 31;
    if (warp >= NN) return;
    const int n = warp;

    float4 xr4 = *(const float4*)&g_xr[(long long)n * 128 + lane * 4];
    float4 w4  = *(const float4*)&att[lane * 4];

    int beg = g_off[n];
    int end = beg + g_deg[n];

    float ssum = 0.0f;
    float4 acc = make_float4(0.f, 0.f, 0.f, 0.f);

    int i = beg;
    for (; i + 3 < end; i += 4) {
        int s0 = __ldg(&g_psrc[i]),     s1 = __ldg(&g_psrc[i + 1]);
        int s2 = __ldg(&g_psrc[i + 2]), s3 = __ldg(&g_psrc[i + 3]);
        float4 v0 = __ldg((const float4*)&g_xl[(long long)s0 * 128 + lane * 4]);
        float4 v1 = __ldg((const float4*)&g_xl[(long long)s1 * 128 + lane * 4]);
        float4 v2 = __ldg((const float4*)&g_xl[(long long)s2 * 128 + lane * 4]);
        float4 v3 = __ldg((const float4*)&g_xl[(long long)s3 * 128 + lane * 4]);
        float p0 = edge_dot(v0, xr4, w4);
        float p1 = edge_dot(v1, xr4, w4);
        float p2 = edge_dot(v2, xr4, w4);
        float p3 = edge_dot(v3, xr4, w4);
#pragma unroll
        for (int o = 16; o > 0; o >>= 1) {
            p0 += __shfl_xor_sync(0xffffffffu, p0, o);
            p1 += __shfl_xor_sync(0xffffffffu, p1, o);
            p2 += __shfl_xor_sync(0xffffffffu, p2, o);
            p3 += __shfl_xor_sync(0xffffffffu, p3, o);
        }
        float w0 = __expf(p0), w1 = __expf(p1), w2 = __expf(p2), w3 = __expf(p3);
        ssum += (w0 + w1) + (w2 + w3);
        acc.x = fmaf(w0, v0.x, fmaf(w1, v1.x, fmaf(w2, v2.x, fmaf(w3, v3.x, acc.x))));
        acc.y = fmaf(w0, v0.y, fmaf(w1, v1.y, fmaf(w2, v2.y, fmaf(w3, v3.y, acc.y))));
        acc.z = fmaf(w0, v0.z, fmaf(w1, v1.z, fmaf(w2, v2.z, fmaf(w3, v3.z, acc.z))));
        acc.w = fmaf(w0, v0.w, fmaf(w1, v1.w, fmaf(w2, v2.w, fmaf(w3, v3.w, acc.w))));
    }
    for (; i < end; i++) {
        int s = __ldg(&g_psrc[i]);
        float4 v = __ldg((const float4*)&g_xl[(long long)s * 128 + lane * 4]);
        float pe = edge_dot(v, xr4, w4);
#pragma unroll
        for (int o = 16; o > 0; o >>= 1) pe += __shfl_xor_sync(0xffffffffu, pe, o);
        float wgt = __expf(pe);
        ssum += wgt;
        acc.x = fmaf(wgt, v.x, acc.x);
        acc.y = fmaf(wgt, v.y, acc.y);
        acc.z = fmaf(wgt, v.z, acc.z);
        acc.w = fmaf(wgt, v.w, acc.w);
    }

    float inv = 1.0f / (ssum + 1e-16f);
    float4 b4 = *(const float4*)&bias[lane * 4];
    float4 o;
    o.x = fmaf(acc.x, inv, b4.x);
    o.y = fmaf(acc.y, inv, b4.y);
    o.z = fmaf(acc.z, inv, b4.z);
    o.w = fmaf(acc.w, inv, b4.w);

    if (sel == 2) {
        *(float4*)&outp[(long long)n * 128 + lane * 4] = o;
    } else {
        o.x = fmaxf(o.x, 0.f); o.y = fmaxf(o.y, 0.f);
        o.z = fmaxf(o.z, 0.f); o.w = fmaxf(o.w, 0.f);
        __nv_bfloat16 hx, hy, hz, hw, lx, ly, lz, lw;
        split1(o.x, hx, lx); split1(o.y, hy, ly);
        split1(o.z, hz, lz); split1(o.w, hw, lw);
        __nv_bfloat162* ph = (__nv_bfloat162*)&g_Ah[n * 128 + lane * 4];
        __nv_bfloat162* pl = (__nv_bfloat162*)&g_Al[n * 128 + lane * 4];
        ph[0] = __nv_bfloat162(hx, hy); ph[1] = __nv_bfloat162(hz, hw);
        pl[0] = __nv_bfloat162(lx, ly); pl[1] = __nv_bfloat162(lz, lw);
    }
}

// ---------------- host ------------------------------------------------------
extern "C" void kernel_launch(void* const* d_in, const int* in_sizes, int n_in,
                              void* d_out, int out_size)
{
    const float* x   = (const float*)d_in[0];
    const float* Wl  = (const float*)d_in[1];
    const float* Wr  = (const float*)d_in[2];
    const float* att = (const float*)d_in[3];
    const float* b   = (const float*)d_in[4];
    const void*  ei  = d_in[5];
    float* outp = (float*)d_out;

    cudaFuncSetAttribute(gemm_pers, cudaFuncAttributeMaxDynamicSharedMemorySize, GEMM_SMEM);
    void* degPtr = nullptr;
    cudaGetSymbolAddress(&degPtr, g_deg);

    dim3 gemmGrid(148, 2);
    int nodeBlocks = (NN * 32 + 63) / 64;

    cudaStream_t side = nullptr;
    cudaEvent_t eF = nullptr, eJ = nullptr;
    bool forked =
        (cudaStreamCreateWithFlags(&side, cudaStreamNonBlocking) == cudaSuccess) &&
        (cudaEventCreateWithFlags(&eF, cudaEventDisableTiming) == cudaSuccess) &&
        (cudaEventCreateWithFlags(&eJ, cudaEventDisableTiming) == cudaSuccess);

    if (forked) {
        cudaEventRecord(eF, 0);
        cudaStreamWaitEvent(side, eF, 0);
        // side branch: CSR build
        cudaMemsetAsync(degPtr, 0, NN * sizeof(int), side);
        detect_kernel<<<1, 256, 0, side>>>((const int*)ei);
        convert_hist<<<(2 * EE + 255) / 256, 256, 0, side>>>(ei);
        blocksum_kernel<<<NB, 256, 0, side>>>();
        scanbsum_kernel<<<1, 512, 0, side>>>();
        binscan_kernel<<<NB, 256, 0, side>>>();
        scatter_kernel<<<(EE + 255) / 256, 256, 0, side>>>();
        cudaEventRecord(eJ, side);
        // main branch: weight/input conversion + layer-0 GEMM
        conv_W<<<384, 256>>>(Wl, Wr);
        conv_x<<<(NN * 32 + 255) / 256, 256>>>(x);
        gemm_pers<<<gemmGrid, 256, GEMM_SMEM>>>(0);
        cudaStreamWaitEvent(0, eJ, 0);
    } else {
        cudaMemsetAsync(degPtr, 0, NN * sizeof(int));
        detect_kernel<<<1, 256>>>((const int*)ei);
        convert_hist<<<(2 * EE + 255) / 256, 256>>>(ei);
        blocksum_kernel<<<NB, 256>>>();
        scanbsum_kernel<<<1, 512>>>();
        binscan_kernel<<<NB, 256>>>();
        scatter_kernel<<<(EE + 255) / 256, 256>>>();
        conv_W<<<384, 256>>>(Wl, Wr);
        conv_x<<<(NN * 32 + 255) / 256, 256>>>(x);
        gemm_pers<<<gemmGrid, 256, GEMM_SMEM>>>(0);
    }

    node_fused<<<nodeBlocks, 64>>>(att, b, outp, 0);

    for (int layer = 1; layer < 3; layer++) {
        gemm_pers<<<gemmGrid, 256, GEMM_SMEM>>>(layer);
        node_fused<<<nodeBlocks, 64>>>(att + layer * DD, b + layer * DD, outp, layer);
    }
    // side stream/events intentionally not destroyed (capture-safe; see R9 note)
}

// round 16
// speedup vs baseline: 1.0800x; 1.0800x over previous
#include <cuda_runtime.h>
#include <cuda_bf16.h>
#include <math_constants.h>
#include <cstdint>

#define NN 100000
#define NPAD 100096          // 782 * 128 = 1564 * 64
#define DD 128
#define EE 1600000
#define NEG_SLOPE 0.2f
#define NB ((NN + 255) / 256)

// ---------------- scratch (device globals; no runtime allocation) ----------
__device__ float g_xl[NPAD * DD];
__device__ float g_xr[NPAD * DD];
__device__ __nv_bfloat16 g_Ah[NPAD * DD];
__device__ __nv_bfloat16 g_Al[NPAD * DD];
__device__ __nv_bfloat16 g_Bh[6][DD * DD];  // W^T [n][k] row-major, hi
__device__ __nv_bfloat16 g_Bl[6][DD * DD];  // ... lo
__device__ int   g_src[EE];
__device__ int   g_dst[EE];
__device__ int   g_deg[NN];
__device__ int   g_off[NN];
__device__ int   g_cur[NN];
__device__ int   g_psrc[EE];
__device__ int   g_bsum[NB];
__device__ int   g_bbase[512];
__device__ int   g_is64;

// ---------------- helpers ----------------------------------------------------
__device__ __forceinline__ uint32_t smem_u32(const void* p) {
    uint32_t a;
    asm("{ .reg .u64 t; cvta.to.shared.u64 t, %1; cvt.u32.u64 %0, t; }" : "=r"(a) : "l"(p));
    return a;
}
__device__ __forceinline__ void ldmatrix_x4(uint32_t& r0, uint32_t& r1,
                                            uint32_t& r2, uint32_t& r3, uint32_t addr) {
    asm volatile("ldmatrix.sync.aligned.m8n8.x4.shared.b16 {%0,%1,%2,%3}, [%4];"
        : "=r"(r0), "=r"(r1), "=r"(r2), "=r"(r3) : "r"(addr));
}
__device__ __forceinline__ void mma_bf16(float* c, const uint32_t* a, const uint32_t* b) {
    asm volatile("mma.sync.aligned.m16n8k16.row.col.f32.bf16.bf16.f32 "
        "{%0,%1,%2,%3}, {%4,%5,%6,%7}, {%8,%9}, {%0,%1,%2,%3};"
        : "+f"(c[0]), "+f"(c[1]), "+f"(c[2]), "+f"(c[3])
        : "r"(a[0]), "r"(a[1]), "r"(a[2]), "r"(a[3]), "r"(b[0]), "r"(b[1]));
}
__device__ __forceinline__ void cp_async16(uint32_t saddr, const void* gptr) {
    asm volatile("cp.async.cg.shared.global [%0], [%1], 16;" :: "r"(saddr), "l"(gptr));
}
__device__ __forceinline__ void cp_commit() {
    asm volatile("cp.async.commit_group;");
}
template <int N>
__device__ __forceinline__ void cp_wait() {
    asm volatile("cp.async.wait_group %0;" :: "n"(N));
}
__device__ __forceinline__ void split1(float v, __nv_bfloat16& hi, __nv_bfloat16& lo) {
    hi = __float2bfloat16(v);
    lo = __float2bfloat16(v - __bfloat162float(hi));
}

// ---------------- dtype detection + fused convert/hist ---------------------
__global__ void detect_kernel(const int* __restrict__ ei32) {
    int t = threadIdx.x;
    int v = ei32[2 * t + 1];
    unsigned ok = __ballot_sync(0xffffffffu, v == 0);
    __shared__ int nz;
    if (t == 0) nz = 0;
    __syncthreads();
    if ((t & 31) == 0 && ok != 0xffffffffu) atomicAdd(&nz, 1);
    __syncthreads();
    if (t == 0) g_is64 = (nz == 0) ? 1 : 0;
}

// g_deg must be zeroed (memsetAsync) before this runs
__global__ void convert_hist(const void* __restrict__ ei) {
    int i = blockIdx.x * blockDim.x + threadIdx.x;
    if (i >= 2 * EE) return;
    int v;
    if (g_is64) v = (int)((const long long*)ei)[i];
    else        v = ((const int*)ei)[i];
    if (i < EE) g_src[i] = v;
    else { g_dst[i - EE] = v; atomicAdd(&g_deg[v], 1); }
}

__global__ void blocksum_kernel() {
    int b = blockIdx.x * 256 + threadIdx.x;
    int d = (b < NN) ? g_deg[b] : 0;
#pragma unroll
    for (int o = 16; o > 0; o >>= 1) d += __shfl_xor_sync(0xffffffffu, d, o);
    __shared__ int ws[8];
    if ((threadIdx.x & 31) == 0) ws[threadIdx.x >> 5] = d;
    __syncthreads();
    if (threadIdx.x == 0) {
        int t = 0;
#pragma unroll
        for (int i = 0; i < 8; i++) t += ws[i];
        g_bsum[blockIdx.x] = t;
    }
}

__global__ void scanbsum_kernel() {
    __shared__ int s[512];
    int t = threadIdx.x;
    int v = (t < NB) ? g_bsum[t] : 0;
    s[t] = v;
    __syncthreads();
    for (int o = 1; o < 512; o <<= 1) {
        int a = (t >= o) ? s[t - o] : 0;
        __syncthreads();
        s[t] += a;
        __syncthreads();
    }
    g_bbase[t] = s[t] - v;
}

__global__ void binscan_kernel() {
    __shared__ int s[256];
    int t = threadIdx.x;
    int b = blockIdx.x * 256 + t;
    int d = (b < NN) ? g_deg[b] : 0;
    s[t] = d;
    __syncthreads();
    for (int o = 1; o < 256; o <<= 1) {
        int a = (t >= o) ? s[t - o] : 0;
        __syncthreads();
        s[t] += a;
        __syncthreads();
    }
    if (b < NN) {
        int off = g_bbase[blockIdx.x] + s[t] - d;
        g_off[b] = off;
        g_cur[b] = off;
    }
}

__global__ void scatter_kernel() {
    int e = blockIdx.x * blockDim.x + threadIdx.x;
    if (e >= EE) return;
    int d = g_dst[e];
    int pos = atomicAdd(&g_cur[d], 1);
    g_psrc[pos] = g_src[e];
}

// ---------------- W conversion: transpose + split ---------------------------
__global__ void conv_W(const float* __restrict__ Wl, const float* __restrict__ Wr) {
    int idx = blockIdx.x * 256 + threadIdx.x;   // 0..98303
    int m = idx >> 14;
    int r = idx & 16383;
    int k = r >> 7;
    int n = r & 127;
    int layer = m >> 1;
    const float* src = (m & 1) ? Wr : Wl;
    float v = src[layer * 16384 + k * 128 + n];
    __nv_bfloat16 hi, lo;
    split1(v, hi, lo);
    g_Bh[m][n * 128 + k] = hi;
    g_Bl[m][n * 128 + k] = lo;
}

// ---------------- x conversion (layer 0 A input) ---------------------------
__global__ void conv_x(const float* __restrict__ x) {
    int idx = blockIdx.x * blockDim.x + threadIdx.x;
    if (idx >= NN * 32) return;
    float4 v = ((const float4*)x)[idx];
    __nv_bfloat16 hx, hy, hz, hw, lx, ly, lz, lw;
    split1(v.x, hx, lx); split1(v.y, hy, ly);
    split1(v.z, hz, lz); split1(v.w, hw, lw);
    __nv_bfloat162* ph = (__nv_bfloat162*)g_Ah + idx * 2;
    __nv_bfloat162* pl = (__nv_bfloat162*)g_Al + idx * 2;
    ph[0] = __nv_bfloat162(hx, hy); ph[1] = __nv_bfloat162(hz, hw);
    pl[0] = __nv_bfloat162(lx, ly); pl[1] = __nv_bfloat162(lz, lw);
}

// ---------------- persistent tensor-core GEMM, 64-row blocks ---------------
// Grid (148, 2), 2 CTA/SM, one wave. B (hi+lo) loaded ONCE per CTA into a
// persistent smem region (272B row stride); A double-buffered via cp.async.
// 64-row blocks: 1564 blocks / 148 CTAs -> ~4% tail imbalance (vs 14% @128),
// warp tile 32x32 -> acc 32 regs.
#define CROW 80
#define A_SEG 5120
#define A_BUF 10240
#define B_OFF 20480
#define B_TYPE 34816
#define GEMM_SMEM 90112

__global__ void __launch_bounds__(256, 2) gemm_pers(int layer) {
    extern __shared__ char smem[];
    const int tid = threadIdx.x;
    const int wid = tid >> 5;
    const int lane = tid & 31;
    const int mat = layer * 2 + blockIdx.y;

    const int m0 = (wid >> 2) * 32;     // 0 or 32
    const int n0 = (wid & 3) * 32;      // 0,32,64,96

    const uint32_t sbase = smem_u32(smem);
    const uint32_t a_row = m0 + (lane & 15);
    const uint32_t a_coff = ((lane >> 4) << 4);
    const int quad = lane >> 3;
    const uint32_t b_row = n0 + ((quad >> 1) << 3) + (lane & 7);
    const uint32_t b_coff = ((quad & 1) << 4);

    const char* aHg = (const char*)g_Ah;
    const char* aLg = (const char*)g_Al;
    const char* bHg = (const char*)g_Bh[mat];
    const char* bLg = (const char*)g_Bl[mat];

    // one-time persistent B load: 2 types x 128 rows x 16 chunks of 16B
#pragma unroll
    for (int p = 0; p < 16; p++) {
        int o = tid + p * 256;          // 0..4095
        int type = o >> 11;
        int r = (o >> 4) & 127;
        int cg = o & 15;
        const char* g = (type ? bLg : bHg) + r * 256 + cg * 16;
        cp_async16(sbase + B_OFF + type * B_TYPE + r * 272 + cg * 16, g);
    }
    cp_commit();

    float* __restrict__ C = (blockIdx.y == 0) ? g_xl : g_xr;

    for (int rb = blockIdx.x; rb < NPAD / 64; rb += 148) {
        const int rowBase = rb * 64;

        float acc[2][4][4];
#pragma unroll
        for (int i = 0; i < 2; i++)
#pragma unroll
            for (int j = 0; j < 4; j++)
#pragma unroll
                for (int q = 0; q < 4; q++) acc[i][j][q] = 0.0f;

        auto load_chunk = [&](int kc, int buf) {
#pragma unroll
            for (int p = 0; p < 2; p++) {
                int o = tid + p * 256;      // 0..511
                int seg = o >> 8;           // 0 = AH, 1 = AL
                int r = (o >> 2) & 63;
                int j = o & 3;
                const char* g = (seg ? aLg : aHg)
                    + ((long long)(rowBase + r) * 256 + kc * 64 + j * 16);
                cp_async16(sbase + buf * A_BUF + seg * A_SEG + r * CROW + j * 16, g);
            }
            cp_commit();
        };

        load_chunk(0, 0);

#pragma unroll
        for (int kc = 0; kc < 4; kc++) {
            if (kc < 3) load_chunk(kc + 1, (kc + 1) & 1);
            if (kc < 3) cp_wait<1>(); else cp_wait<0>();
            __syncthreads();

            const uint32_t ab = sbase + (kc & 1) * A_BUF;
#pragma unroll
            for (int ks = 0; ks < 2; ks++) {
                const uint32_t k0b = ks * 32;
                uint32_t bHf[4][2], bLf[4][2];
#pragma unroll
                for (int p = 0; p < 2; p++) {
                    uint32_t bd = sbase + B_OFF + (b_row + p * 16) * 272
                                + kc * 64 + k0b + b_coff;
                    uint32_t r0, r1, r2, r3;
                    ldmatrix_x4(r0, r1, r2, r3, bd);
                    bHf[p * 2][0] = r0; bHf[p * 2][1] = r1;
                    bHf[p * 2 + 1][0] = r2; bHf[p * 2 + 1][1] = r3;
                    ldmatrix_x4(r0, r1, r2, r3, bd + B_TYPE);
                    bLf[p * 2][0] = r0; bLf[p * 2][1] = r1;
                    bLf[p * 2 + 1][0] = r2; bLf[p * 2 + 1][1] = r3;
                }
#pragma unroll
                for (int mi = 0; mi < 2; mi++) {
                    uint32_t aHf[4], aLf[4];
                    uint32_t ad = ab + (a_row + mi * 16) * CROW + k0b + a_coff;
                    ldmatrix_x4(aHf[0], aHf[1], aHf[2], aHf[3], ad);
                    ldmatrix_x4(aLf[0], aLf[1], aLf[2], aLf[3], ad + A_SEG);
#pragma unroll
                    for (int ni = 0; ni < 4; ni++) {
                        mma_bf16(acc[mi][ni], aHf, bHf[ni]);
                        mma_bf16(acc[mi][ni], aLf, bHf[ni]);
                        mma_bf16(acc[mi][ni], aHf, bLf[ni]);
                    }
                }
            }
            if (kc < 3) __syncthreads();   // last chunk: epilogue touches no smem
        }

#pragma unroll
        for (int mi = 0; mi < 2; mi++) {
#pragma unroll
            for (int ni = 0; ni < 4; ni++) {
                int row0 = rowBase + m0 + mi * 16 + (lane >> 2);
                int col = n0 + ni * 8 + (lane & 3) * 2;
                if (row0 < NN)
                    *(float2*)&C[row0 * 128 + col] = make_float2(acc[mi][ni][0], acc[mi][ni][1]);
                int row1 = row0 + 8;
                if (row1 < NN)
                    *(float2*)&C[row1 * 128 + col] = make_float2(acc[mi][ni][2], acc[mi][ni][3]);
            }
        }
        __syncthreads();   // all warps done with A buf reads before next rb reload
    }
}

// ---------------- fused node kernel: zero-reference softmax, unroll-4 ------
__device__ __forceinline__ float edge_dot(float4 v, float4 xr4, float4 w4) {
    float z, p;
    z = v.x + xr4.x; z = (z > 0.f) ? z : NEG_SLOPE * z; p = z * w4.x;
    z = v.y + xr4.y; z = (z > 0.f) ? z : NEG_SLOPE * z; p = fmaf(z, w4.y, p);
    z = v.z + xr4.z; z = (z > 0.f) ? z : NEG_SLOPE * z; p = fmaf(z, w4.z, p);
    z = v.w + xr4.w; z = (z > 0.f) ? z : NEG_SLOPE * z; p = fmaf(z, w4.w, p);
    return p;
}

__global__ void __launch_bounds__(64) node_fused(
    const float* __restrict__ att,
    const float* __restrict__ bias,
    float* __restrict__ outp, int sel)
{
    int warp = (blockIdx.x * blockDim.x + threadIdx.x) >> 5;
    int lane = threadIdx.x & 31;
    if (warp >= NN) return;
    const int n = warp;

    float4 xr4 = *(const float4*)&g_xr[(long long)n * 128 + lane * 4];
    float4 w4  = *(const float4*)&att[lane * 4];

    int beg = g_off[n];
    int end = beg + g_deg[n];

    float ssum = 0.0f;
    float4 acc = make_float4(0.f, 0.f, 0.f, 0.f);

    int i = beg;
    for (; i + 3 < end; i += 4) {
        int s0 = __ldg(&g_psrc[i]),     s1 = __ldg(&g_psrc[i + 1]);
        int s2 = __ldg(&g_psrc[i + 2]), s3 = __ldg(&g_psrc[i + 3]);
        float4 v0 = __ldg((const float4*)&g_xl[(long long)s0 * 128 + lane * 4]);
        float4 v1 = __ldg((const float4*)&g_xl[(long long)s1 * 128 + lane * 4]);
        float4 v2 = __ldg((const float4*)&g_xl[(long long)s2 * 128 + lane * 4]);
        float4 v3 = __ldg((const float4*)&g_xl[(long long)s3 * 128 + lane * 4]);
        float p0 = edge_dot(v0, xr4, w4);
        float p1 = edge_dot(v1, xr4, w4);
        float p2 = edge_dot(v2, xr4, w4);
        float p3 = edge_dot(v3, xr4, w4);
#pragma unroll
        for (int o = 16; o > 0; o >>= 1) {
            p0 += __shfl_xor_sync(0xffffffffu, p0, o);
            p1 += __shfl_xor_sync(0xffffffffu, p1, o);
            p2 += __shfl_xor_sync(0xffffffffu, p2, o);
            p3 += __shfl_xor_sync(0xffffffffu, p3, o);
        }
        float w0 = __expf(p0), w1 = __expf(p1), w2 = __expf(p2), w3 = __expf(p3);
        ssum += (w0 + w1) + (w2 + w3);
        acc.x = fmaf(w0, v0.x, fmaf(w1, v1.x, fmaf(w2, v2.x, fmaf(w3, v3.x, acc.x))));
        acc.y = fmaf(w0, v0.y, fmaf(w1, v1.y, fmaf(w2, v2.y, fmaf(w3, v3.y, acc.y))));
        acc.z = fmaf(w0, v0.z, fmaf(w1, v1.z, fmaf(w2, v2.z, fmaf(w3, v3.z, acc.z))));
        acc.w = fmaf(w0, v0.w, fmaf(w1, v1.w, fmaf(w2, v2.w, fmaf(w3, v3.w, acc.w))));
    }
    for (; i < end; i++) {
        int s = __ldg(&g_psrc[i]);
        float4 v = __ldg((const float4*)&g_xl[(long long)s * 128 + lane * 4]);
        float pe = edge_dot(v, xr4, w4);
#pragma unroll
        for (int o = 16; o > 0; o >>= 1) pe += __shfl_xor_sync(0xffffffffu, pe, o);
        float wgt = __expf(pe);
        ssum += wgt;
        acc.x = fmaf(wgt, v.x, acc.x);
        acc.y = fmaf(wgt, v.y, acc.y);
        acc.z = fmaf(wgt, v.z, acc.z);
        acc.w = fmaf(wgt, v.w, acc.w);
    }

    float inv = 1.0f / (ssum + 1e-16f);
    float4 b4 = *(const float4*)&bias[lane * 4];
    float4 o;
    o.x = fmaf(acc.x, inv, b4.x);
    o.y = fmaf(acc.y, inv, b4.y);
    o.z = fmaf(acc.z, inv, b4.z);
    o.w = fmaf(acc.w, inv, b4.w);

    if (sel == 2) {
        *(float4*)&outp[(long long)n * 128 + lane * 4] = o;
    } else {
        o.x = fmaxf(o.x, 0.f); o.y = fmaxf(o.y, 0.f);
        o.z = fmaxf(o.z, 0.f); o.w = fmaxf(o.w, 0.f);
        __nv_bfloat16 hx, hy, hz, hw, lx, ly, lz, lw;
        split1(o.x, hx, lx); split1(o.y, hy, ly);
        split1(o.z, hz, lz); split1(o.w, hw, lw);
        __nv_bfloat162* ph = (__nv_bfloat162*)&g_Ah[n * 128 + lane * 4];
        __nv_bfloat162* pl = (__nv_bfloat162*)&g_Al[n * 128 + lane * 4];
        ph[0] = __nv_bfloat162(hx, hy); ph[1] = __nv_bfloat162(hz, hw);
        pl[0] = __nv_bfloat162(lx, ly); pl[1] = __nv_bfloat162(lz, lw);
    }
}

// ---------------- host ------------------------------------------------------
extern "C" void kernel_launch(void* const* d_in, const int* in_sizes, int n_in,
                              void* d_out, int out_size)
{
    const float* x   = (const float*)d_in[0];
    const float* Wl  = (const float*)d_in[1];
    const float* Wr  = (const float*)d_in[2];
    const float* att = (const float*)d_in[3];
    const float* b   = (const float*)d_in[4];
    const void*  ei  = d_in[5];
    float* outp = (float*)d_out;

    cudaFuncSetAttribute(gemm_pers, cudaFuncAttributeMaxDynamicSharedMemorySize, GEMM_SMEM);
    void* degPtr = nullptr;
    cudaGetSymbolAddress(&degPtr, g_deg);

    dim3 gemmGrid(148, 2);
    int nodeBlocks = (NN * 32 + 63) / 64;

    cudaStream_t side = nullptr;
    cudaEvent_t eF = nullptr, eJ = nullptr;
    bool forked =
        (cudaStreamCreateWithFlags(&side, cudaStreamNonBlocking) == cudaSuccess) &&
        (cudaEventCreateWithFlags(&eF, cudaEventDisableTiming) == cudaSuccess) &&
        (cudaEventCreateWithFlags(&eJ, cudaEventDisableTiming) == cudaSuccess);

    if (forked) {
        cudaEventRecord(eF, 0);
        cudaStreamWaitEvent(side, eF, 0);
        // side branch: CSR build
        cudaMemsetAsync(degPtr, 0, NN * sizeof(int), side);
        detect_kernel<<<1, 256, 0, side>>>((const int*)ei);
        convert_hist<<<(2 * EE + 255) / 256, 256, 0, side>>>(ei);
        blocksum_kernel<<<NB, 256, 0, side>>>();
        scanbsum_kernel<<<1, 512, 0, side>>>();
        binscan_kernel<<<NB, 256, 0, side>>>();
        scatter_kernel<<<(EE + 255) / 256, 256, 0, side>>>();
        cudaEventRecord(eJ, side);
        // main branch: weight/input conversion + layer-0 GEMM
        conv_W<<<384, 256>>>(Wl, Wr);
        conv_x<<<(NN * 32 + 255) / 256, 256>>>(x);
        gemm_pers<<<gemmGrid, 256, GEMM_SMEM>>>(0);
        cudaStreamWaitEvent(0, eJ, 0);
    } else {
        cudaMemsetAsync(degPtr, 0, NN * sizeof(int));
        detect_kernel<<<1, 256>>>((const int*)ei);
        convert_hist<<<(2 * EE + 255) / 256, 256>>>(ei);
        blocksum_kernel<<<NB, 256>>>();
        scanbsum_kernel<<<1, 512>>>();
        binscan_kernel<<<NB, 256>>>();
        scatter_kernel<<<(EE + 255) / 256, 256>>>();
        conv_W<<<384, 256>>>(Wl, Wr);
        conv_x<<<(NN * 32 + 255) / 256, 256>>>(x);
        gemm_pers<<<gemmGrid, 256, GEMM_SMEM>>>(0);
    }

    node_fused<<<nodeBlocks, 64>>>(att, b, outp, 0);

    for (int layer = 1; layer < 3; layer++) {
        gemm_pers<<<gemmGrid, 256, GEMM_SMEM>>>(layer);
        node_fused<<<nodeBlocks, 64>>>(att + layer * DD, b + layer * DD, outp, layer);
    }
    // side stream/events intentionally not destroyed (capture-safe; see R9 note)
}